// round 3
// baseline (speedup 1.0000x reference)
#include <cuda_runtime.h>

// Problem constants
#define TT 512
#define DD 16
#define HH 48
#define NB 16          // batch per CTA
#define NBI 4          // batch per group
#define NTHREADS 384   // 48 j * 2 gate-pairs * 4 groups
#define NCTA 128

// SMEM byte offsets
#define W1I_B 0                          // [16][48][4g] float
#define W1R_B (W1I_B + DD*HH*4*4)        // [48][48][4g]
#define W2I_B (W1R_B + HH*HH*4*4)
#define W2R_B (W2I_B + HH*HH*4*4)
#define B1_B  (W2R_B + HH*HH*4*4)        // [48][4]
#define B2_B  (B1_B + HH*4*4)
#define H1_B  (B2_B + HH*4*4)            // [2][16][48][2] float (dup'd)
#define H2_B  (H1_B + 2*NB*HH*2*4)
#define XD_B  (H2_B + 2*NB*HH*2*4)       // [2][16][16][2] float (dup'd)
#define SMEM_BYTES (XD_B + 2*NB*DD*2*4)

#define HBUF_STRIDE (NB*HH*2*4)          // 6144 B
#define XBUF_STRIDE (NB*DD*2*4)          // 2048 B

typedef unsigned long long ull;

__device__ __forceinline__ float fsig(float x) {
    return __fdividef(1.0f, 1.0f + __expf(-x));
}
__device__ __forceinline__ float ftanh_(float x) {
    return __fdividef(2.0f, 1.0f + __expf(-2.0f * x)) - 1.0f;
}
__device__ __forceinline__ void ffma2(ull& a, ull w, ull h) {
    asm("fma.rn.f32x2 %0, %1, %2, %0;" : "+l"(a) : "l"(w), "l"(h));
}
__device__ __forceinline__ float2 unpk(ull v) {
    float2 r;
    asm("mov.b64 {%0, %1}, %2;" : "=f"(r.x), "=f"(r.y) : "l"(v));
    return r;
}
__device__ __forceinline__ void sts_dup(char* p, float v) {
    ull d;
    asm("mov.b64 %0, {%1, %1};" : "=l"(d) : "f"(v));
    *(ull*)p = d;
}

__global__ void __launch_bounds__(NTHREADS, 1)
lstm2_kernel(const float* __restrict__ x,
             const float* __restrict__ Wih0, const float* __restrict__ Whh0,
             const float* __restrict__ bih0, const float* __restrict__ bhh0,
             const float* __restrict__ Wih1, const float* __restrict__ Whh1,
             const float* __restrict__ bih1, const float* __restrict__ bhh1,
             const float* __restrict__ fcw,  const float* __restrict__ fcb,
             float* __restrict__ out)
{
    extern __shared__ char sm[];
    float* smf = (float*)sm;
    const int tid = threadIdx.x;

    // ---- weight repack: W[g*HH+j][k] -> [k][j][4g] ----
    for (int i = tid; i < DD*HH*4; i += NTHREADS) {
        int g = i & 3, jj = (i >> 2) % HH, k = i / (HH*4);
        smf[(W1I_B >> 2) + i] = Wih0[(g*HH + jj)*DD + k];
    }
    for (int i = tid; i < HH*HH*4; i += NTHREADS) {
        int g = i & 3, jj = (i >> 2) % HH, k = i / (HH*4);
        int r = (g*HH + jj)*HH + k;
        smf[(W1R_B >> 2) + i] = Whh0[r];
        smf[(W2I_B >> 2) + i] = Wih1[r];
        smf[(W2R_B >> 2) + i] = Whh1[r];
    }
    for (int i = tid; i < HH*4; i += NTHREADS) {
        int g = i & 3, jj = i >> 2;
        smf[(B1_B >> 2) + i] = bih0[g*HH + jj] + bhh0[g*HH + jj];
        smf[(B2_B >> 2) + i] = bih1[g*HH + jj] + bhh1[g*HH + jj];
    }
    for (int i = tid; i < 2*NB*HH*2*2; i += NTHREADS)
        smf[(H1_B >> 2) + i] = 0.f;   // zeros H1 and H2 (contiguous)

    // ---- lane mapping: gp=bit0, j_low=bits1..3, grp_low=bit4 ----
    const int gp = tid & 1;           // gate pair: 0 -> {i,f}, 1 -> {g,o}
    const int jl = (tid >> 1) & 7;
    const int gh = (tid >> 4) & 1;
    const int w  = tid >> 5;          // warp 0..11
    const int j  = (w % 6) * 8 + jl;
    const int grp = (w / 6) * 2 + gh;
    const int bl0 = grp * NBI;

    const float* xg = x + ((long)blockIdx.x * NB) * (long)(TT*DD);

    // stage x[0] (dup'd) into buf 0
    const int xb_ = tid >> 4, xd = tid & 15;
    if (tid < NB*DD)
        sts_dup(sm + XD_B + ((xb_*DD + xd) << 3), xg[(long)xb_*(TT*DD) + xd]);
    __syncthreads();

    // per-thread weight base pointers (gate-pair slice)
    const char* pW1I = sm + W1I_B + j*16 + gp*8;
    const char* pW1R = sm + W1R_B + j*16 + gp*8;
    const char* pW2I = sm + W2I_B + j*16 + gp*8;
    const char* pW2R = sm + W2R_B + j*16 + gp*8;
    const ull bp1 = *(const ull*)(sm + B1_B + j*16 + gp*8);
    const ull bp2 = *(const ull*)(sm + B2_B + j*16 + gp*8);

    const int ob0 = gp * 2;           // first owned batch element (0 or 2)
    float c1[2] = {0.f, 0.f};
    float c2[2] = {0.f, 0.f};

    for (int t = 0; t <= TT; ++t) {
        const int cur = t & 1, prv = cur ^ 1;

        // prefetch x[t+1] early: LDG overlapped with the whole compute phase
        float xpre = 0.f;
        if (t + 1 < TT && tid < NB*DD)
            xpre = xg[(long)xb_*(TT*DD) + (long)(t+1)*DD + xd];

        ull a1[NBI], a2[NBI];
        #pragma unroll
        for (int bb = 0; bb < NBI; ++bb) { a1[bb] = bp1; a2[bb] = bp2; }

        // ===== layer1 input: x dup'd in SMEM =====
        {
            const char* xb = sm + XD_B + cur*XBUF_STRIDE + (bl0*DD << 3);
            #pragma unroll 4
            for (int k = 0; k < DD; k += 2) {
                const ull w0 = *(const ull*)(pW1I + (k    )*HH*16);
                const ull w1 = *(const ull*)(pW1I + (k + 1)*HH*16);
                #pragma unroll
                for (int bb = 0; bb < NBI; ++bb) {
                    const ulonglong2 xv = *(const ulonglong2*)(xb + ((bb*DD + k) << 3));
                    ffma2(a1[bb], w0, xv.x);
                    ffma2(a1[bb], w1, xv.y);
                }
            }
        }

        // ===== fused recurrent: W1R@h1[t-1], W2I@h1[t-1], W2R@h2[t-2] =====
        {
            const char* h1b = sm + H1_B + prv*HBUF_STRIDE + (bl0*HH << 3);
            const char* h2b = sm + H2_B + cur*HBUF_STRIDE + (bl0*HH << 3);
            #pragma unroll 4
            for (int k = 0; k < HH; k += 2) {
                const ull wa0 = *(const ull*)(pW1R + (k    )*HH*16);
                const ull wa1 = *(const ull*)(pW1R + (k + 1)*HH*16);
                const ull wb0 = *(const ull*)(pW2I + (k    )*HH*16);
                const ull wb1 = *(const ull*)(pW2I + (k + 1)*HH*16);
                const ull wc0 = *(const ull*)(pW2R + (k    )*HH*16);
                const ull wc1 = *(const ull*)(pW2R + (k + 1)*HH*16);
                #pragma unroll
                for (int bb = 0; bb < NBI; ++bb) {
                    const int boff = (bb*HH + k) << 3;
                    const ulonglong2 h1v = *(const ulonglong2*)(h1b + boff);
                    const ulonglong2 h2v = *(const ulonglong2*)(h2b + boff);
                    ffma2(a1[bb], wa0, h1v.x);
                    ffma2(a1[bb], wa1, h1v.y);
                    ffma2(a2[bb], wb0, h1v.x);
                    ffma2(a2[bb], wb1, h1v.y);
                    ffma2(a2[bb], wc0, h2v.x);
                    ffma2(a2[bb], wc1, h2v.y);
                }
            }
        }

        // ===== layer1 epilogue: gate exchange + c/h update for 2 owned bb =====
        if (t < TT) {
            char* h1n = sm + H1_B + cur*HBUF_STRIDE + (bl0*HH << 3);
            ull e1[NBI];
            #pragma unroll
            for (int bb = 0; bb < NBI; ++bb)
                e1[bb] = __shfl_xor_sync(0xFFFFFFFFu, a1[bb], 1);
            #pragma unroll
            for (int o = 0; o < 2; ++o) {
                const int bb = ob0 + o;
                const ull vIF = gp ? e1[bb] : a1[bb];
                const ull vGO = gp ? a1[bb] : e1[bb];
                float2 pif = unpk(vIF), pgo = unpk(vGO);
                float iv = fsig(pif.x), fv = fsig(pif.y);
                float gv = ftanh_(pgo.x), ov = fsig(pgo.y);
                c1[o] = fmaf(fv, c1[o], iv * gv);
                sts_dup(h1n + ((bb*HH + j) << 3), ov * ftanh_(c1[o]));
            }
        }
        // ===== layer2 epilogue =====
        if (t > 0) {
            char* h2n = sm + H2_B + prv*HBUF_STRIDE + (bl0*HH << 3);
            ull e2[NBI];
            #pragma unroll
            for (int bb = 0; bb < NBI; ++bb)
                e2[bb] = __shfl_xor_sync(0xFFFFFFFFu, a2[bb], 1);
            #pragma unroll
            for (int o = 0; o < 2; ++o) {
                const int bb = ob0 + o;
                const ull vIF = gp ? e2[bb] : a2[bb];
                const ull vGO = gp ? a2[bb] : e2[bb];
                float2 pif = unpk(vIF), pgo = unpk(vGO);
                float iv = fsig(pif.x), fv = fsig(pif.y);
                float gv = ftanh_(pgo.x), ov = fsig(pgo.y);
                c2[o] = fmaf(fv, c2[o], iv * gv);
                sts_dup(h2n + ((bb*HH + j) << 3), ov * ftanh_(c2[o]));
            }
        }
        // ===== stage prefetched x[t+1] =====
        if (t + 1 < TT && tid < NB*DD)
            sts_dup(sm + XD_B + prv*XBUF_STRIDE + ((xb_*DD + xd) << 3), xpre);
        __syncthreads();
    }

    // ===== final FC + sigmoid: h2[511] in buf 1 (dup'd layout) =====
    if (tid < NB) {
        const float* h2f = (const float*)(sm + H2_B + 1*HBUF_STRIDE) + tid*HH*2;
        float acc = fcb[0];
        #pragma unroll
        for (int jj = 0; jj < HH; ++jj)
            acc = fmaf(h2f[jj*2], fcw[jj], acc);
        out[blockIdx.x * NB + tid] = fsig(acc);
    }
}

extern "C" void kernel_launch(void* const* d_in, const int* in_sizes, int n_in,
                              void* d_out, int out_size) {
    (void)in_sizes; (void)n_in; (void)out_size;
    cudaFuncSetAttribute(lstm2_kernel,
                         cudaFuncAttributeMaxDynamicSharedMemorySize, SMEM_BYTES);
    lstm2_kernel<<<NCTA, NTHREADS, SMEM_BYTES>>>(
        (const float*)d_in[0],
        (const float*)d_in[1], (const float*)d_in[2],
        (const float*)d_in[3], (const float*)d_in[4],
        (const float*)d_in[5], (const float*)d_in[6],
        (const float*)d_in[7], (const float*)d_in[8],
        (const float*)d_in[9], (const float*)d_in[10],
        (float*)d_out);
}

// round 4
// speedup vs baseline: 1.3335x; 1.3335x over previous
#include <cuda_runtime.h>

// Problem constants
#define TT 512
#define DD 16
#define HH 48
#define NB 16
#define NBI 4
#define NTHREADS 384   // gp(2) x jl(8) x gh(2) lanes; 12 warps
#define NCTA 128

typedef unsigned long long ull;

// SMEM byte offsets
#define W1I_B 0                   // [8 kp][96 jj2][16B]  {wI_k,wI_k1,wF_k,wF_k1}
#define WR_B  12288               // [24 kp][96 jj2][3 mat][16B]
#define BB1_B (WR_B + 110592)     // [96 jj2][16B] = {bI,0,bF,0}
#define BB2_B (BB1_B + 1536)
#define H1_B  (BB2_B + 1536)      // [2 buf][16 bb][52 floats]
#define H2_B  (H1_B + 2*3328)
#define XD_B  (H2_B + 2*3328)     // [2 buf][16 bb][28 floats]
#define SMEM_BYTES (XD_B + 2*1792)

#define HBUF 3328
#define HROW 208
#define XBUF 1792
#define XROW 112

__device__ __forceinline__ float fsig(float x) {
    return __fdividef(1.0f, 1.0f + __expf(-x));
}
__device__ __forceinline__ float ftanh_(float x) {
    return __fdividef(2.0f, 1.0f + __expf(-2.0f * x)) - 1.0f;
}
__device__ __forceinline__ void ffma2(ull& a, ull w, ull h) {
    asm("fma.rn.f32x2 %0, %1, %2, %0;" : "+l"(a) : "l"(w), "l"(h));
}
__device__ __forceinline__ float2 unpk(ull v) {
    float2 r;
    asm("mov.b64 {%0, %1}, %2;" : "=f"(r.x), "=f"(r.y) : "l"(v));
    return r;
}
__device__ __forceinline__ ull pk2(float a, float b) {
    ull d;
    asm("mov.b64 %0, {%1, %2};" : "=l"(d) : "f"(a), "f"(b));
    return d;
}

__global__ void __launch_bounds__(NTHREADS, 1)
lstm2_kernel(const float* __restrict__ x,
             const float* __restrict__ Wih0, const float* __restrict__ Whh0,
             const float* __restrict__ bih0, const float* __restrict__ bhh0,
             const float* __restrict__ Wih1, const float* __restrict__ Whh1,
             const float* __restrict__ bih1, const float* __restrict__ bhh1,
             const float* __restrict__ fcw,  const float* __restrict__ fcb,
             float* __restrict__ out)
{
    extern __shared__ char sm[];
    float* smf = (float*)sm;
    const int tid = threadIdx.x;

    // ---- repack W1I: dst = kp*384 + jj2*4 + f ; f = g*2+kk ----
    for (int i = tid; i < 8*96*4; i += NTHREADS) {
        int f = i & 3, jj2 = (i >> 2) % 96, kp = i / 384;
        int j = jj2 >> 1, gp = jj2 & 1;
        int gate = gp*2 + (f >> 1), k = kp*2 + (f & 1);
        smf[(W1I_B >> 2) + i] = Wih0[(gate*HH + j)*DD + k];
    }
    // ---- repack WR (W1R=Whh0, W2I=Wih1, W2R=Whh1 interleaved) ----
    for (int i = tid; i < 24*96*3*4; i += NTHREADS) {
        int f = i & 3, m = (i >> 2) % 3, jj2 = (i / 12) % 96, kp = i / 1152;
        int j = jj2 >> 1, gp = jj2 & 1;
        int gate = gp*2 + (f >> 1), k = kp*2 + (f & 1);
        int r = (gate*HH + j)*HH + k;
        smf[(WR_B >> 2) + i] = (m == 0) ? Whh0[r] : (m == 1) ? Wih1[r] : Whh1[r];
    }
    // ---- biases: {b_gate0, 0, b_gate1, 0} per (j,gp) ----
    for (int i = tid; i < 96*4; i += NTHREADS) {
        int f = i & 3, jj2 = i >> 2;
        int j = jj2 >> 1, gp = jj2 & 1;
        int gate = gp*2 + (f >> 1);
        float v1 = (f & 1) ? 0.f : (bih0[gate*HH + j] + bhh0[gate*HH + j]);
        float v2 = (f & 1) ? 0.f : (bih1[gate*HH + j] + bhh1[gate*HH + j]);
        smf[(BB1_B >> 2) + i] = v1;
        smf[(BB2_B >> 2) + i] = v2;
    }
    // ---- zero h buffers (both layers, both bufs) ----
    for (int i = tid; i < (4*HBUF) >> 2; i += NTHREADS)
        smf[(H1_B >> 2) + i] = 0.f;

    // ---- lane mapping: gp=bit0, jl=bits1..3, gh=bit4 ----
    const int gp = tid & 1;
    const int jl = (tid >> 1) & 7;
    const int gh = (tid >> 4) & 1;
    const int w  = tid >> 5;
    const int j  = (w % 6) * 8 + jl;
    const int grp = (w / 6) * 2 + gh;
    const int bl0 = grp * NBI;
    const int jj2 = j*2 + gp;

    const float* xg = x + ((long)blockIdx.x * NB) * (long)(TT*DD);
    const int xb_ = tid >> 4, xd = tid & 15;

    // stage x[0]
    if (tid < NB*DD)
        *(float*)(sm + XD_B + xb_*XROW + xd*4) = xg[(long)xb_*(TT*DD) + xd];
    __syncthreads();

    const char* pWI = sm + W1I_B + jj2*16;
    const char* pWR = sm + WR_B + jj2*48;
    const ulonglong2 b1 = *(const ulonglong2*)(sm + BB1_B + jj2*16);
    const ulonglong2 b2 = *(const ulonglong2*)(sm + BB2_B + jj2*16);

    float c1[2] = {0.f, 0.f};
    float c2[2] = {0.f, 0.f};

    for (int t = 0; t <= TT; ++t) {
        const int cur = t & 1, prv = cur ^ 1;

        // prefetch x[t+1] (overlaps whole compute phase)
        float xpre = 0.f;
        if (t + 1 < TT && tid < NB*DD)
            xpre = xg[(long)xb_*(TT*DD) + (long)(t+1)*DD + xd];

        ull a1I[NBI], a1F[NBI], a2I[NBI], a2F[NBI];
        #pragma unroll
        for (int bb = 0; bb < NBI; ++bb) {
            a1I[bb] = b1.x; a1F[bb] = b1.y;
            a2I[bb] = b2.x; a2F[bb] = b2.y;
        }

        // ===== layer1 input: x plain, k-parity packed =====
        {
            const char* xb = sm + XD_B + cur*XBUF + bl0*XROW;
            #pragma unroll
            for (int kx = 0; kx < 4; ++kx) {
                const ulonglong2 w0 = *(const ulonglong2*)(pWI + (2*kx  )*1536);
                const ulonglong2 w1 = *(const ulonglong2*)(pWI + (2*kx+1)*1536);
                #pragma unroll
                for (int bb = 0; bb < NBI; ++bb) {
                    const ulonglong2 xv = *(const ulonglong2*)(xb + bb*XROW + kx*16);
                    ffma2(a1I[bb], w0.x, xv.x); ffma2(a1F[bb], w0.y, xv.x);
                    ffma2(a1I[bb], w1.x, xv.y); ffma2(a1F[bb], w1.y, xv.y);
                }
            }
        }

        // ===== fused recurrent: W1R@h1[t-1], W2I@h1[t-1], W2R@h2[t-2] =====
        {
            const char* h1b = sm + H1_B + prv*HBUF + bl0*HROW;
            const char* h2b = sm + H2_B + cur*HBUF + bl0*HROW;
            #pragma unroll 2
            for (int kb = 0; kb < 12; ++kb) {
                const char* wb = pWR + kb*9216;
                const ulonglong2 wa0 = *(const ulonglong2*)(wb);
                const ulonglong2 wb0 = *(const ulonglong2*)(wb + 16);
                const ulonglong2 wc0 = *(const ulonglong2*)(wb + 32);
                const ulonglong2 wa1 = *(const ulonglong2*)(wb + 4608);
                const ulonglong2 wb1 = *(const ulonglong2*)(wb + 4624);
                const ulonglong2 wc1 = *(const ulonglong2*)(wb + 4640);
                #pragma unroll
                for (int bb = 0; bb < NBI; ++bb) {
                    const ulonglong2 h1v = *(const ulonglong2*)(h1b + bb*HROW + kb*16);
                    const ulonglong2 h2v = *(const ulonglong2*)(h2b + bb*HROW + kb*16);
                    ffma2(a1I[bb], wa0.x, h1v.x); ffma2(a1F[bb], wa0.y, h1v.x);
                    ffma2(a1I[bb], wa1.x, h1v.y); ffma2(a1F[bb], wa1.y, h1v.y);
                    ffma2(a2I[bb], wb0.x, h1v.x); ffma2(a2F[bb], wb0.y, h1v.x);
                    ffma2(a2I[bb], wb1.x, h1v.y); ffma2(a2F[bb], wb1.y, h1v.y);
                    ffma2(a2I[bb], wc0.x, h2v.x); ffma2(a2F[bb], wc0.y, h2v.x);
                    ffma2(a2I[bb], wc1.x, h2v.y); ffma2(a2F[bb], wc1.y, h2v.y);
                }
            }
        }

        // ===== layer1 epilogue: horizontal add + gate-pair shfl exchange =====
        if (t < TT) {
            char* h1n = sm + H1_B + cur*HBUF + bl0*HROW;
            ull pk[NBI], ex[NBI];
            #pragma unroll
            for (int bb = 0; bb < NBI; ++bb) {
                float2 vI = unpk(a1I[bb]), vF = unpk(a1F[bb]);
                pk[bb] = pk2(vI.x + vI.y, vF.x + vF.y);
            }
            #pragma unroll
            for (int bb = 0; bb < NBI; ++bb)
                ex[bb] = __shfl_xor_sync(0xFFFFFFFFu, pk[bb], 1);
            #pragma unroll
            for (int o = 0; o < 2; ++o) {
                const int bb = gp*2 + o;
                float2 pIF = unpk(gp ? ex[bb] : pk[bb]);
                float2 pGO = unpk(gp ? pk[bb] : ex[bb]);
                float iv = fsig(pIF.x), fv = fsig(pIF.y);
                float gv = ftanh_(pGO.x), ov = fsig(pGO.y);
                c1[o] = fmaf(fv, c1[o], iv * gv);
                *(float*)(h1n + bb*HROW + j*4) = ov * ftanh_(c1[o]);
            }
        }
        // ===== layer2 epilogue =====
        if (t > 0) {
            char* h2n = sm + H2_B + prv*HBUF + bl0*HROW;
            ull pk[NBI], ex[NBI];
            #pragma unroll
            for (int bb = 0; bb < NBI; ++bb) {
                float2 vI = unpk(a2I[bb]), vF = unpk(a2F[bb]);
                pk[bb] = pk2(vI.x + vI.y, vF.x + vF.y);
            }
            #pragma unroll
            for (int bb = 0; bb < NBI; ++bb)
                ex[bb] = __shfl_xor_sync(0xFFFFFFFFu, pk[bb], 1);
            #pragma unroll
            for (int o = 0; o < 2; ++o) {
                const int bb = gp*2 + o;
                float2 pIF = unpk(gp ? ex[bb] : pk[bb]);
                float2 pGO = unpk(gp ? pk[bb] : ex[bb]);
                float iv = fsig(pIF.x), fv = fsig(pIF.y);
                float gv = ftanh_(pGO.x), ov = fsig(pGO.y);
                c2[o] = fmaf(fv, c2[o], iv * gv);
                *(float*)(h2n + bb*HROW + j*4) = ov * ftanh_(c2[o]);
            }
        }
        // ===== stage prefetched x[t+1] =====
        if (t + 1 < TT && tid < NB*DD)
            *(float*)(sm + XD_B + prv*XBUF + xb_*XROW + xd*4) = xpre;
        __syncthreads();
    }

    // ===== final FC + sigmoid: h2[511] in buf 1 =====
    if (tid < NB) {
        const float* h2f = (const float*)(sm + H2_B + HBUF + tid*HROW);
        float acc = fcb[0];
        #pragma unroll
        for (int jj = 0; jj < HH; ++jj)
            acc = fmaf(h2f[jj], fcw[jj], acc);
        out[blockIdx.x * NB + tid] = fsig(acc);
    }
}

extern "C" void kernel_launch(void* const* d_in, const int* in_sizes, int n_in,
                              void* d_out, int out_size) {
    (void)in_sizes; (void)n_in; (void)out_size;
    cudaFuncSetAttribute(lstm2_kernel,
                         cudaFuncAttributeMaxDynamicSharedMemorySize, SMEM_BYTES);
    lstm2_kernel<<<NCTA, NTHREADS, SMEM_BYTES>>>(
        (const float*)d_in[0],
        (const float*)d_in[1], (const float*)d_in[2],
        (const float*)d_in[3], (const float*)d_in[4],
        (const float*)d_in[5], (const float*)d_in[6],
        (const float*)d_in[7], (const float*)d_in[8],
        (const float*)d_in[9], (const float*)d_in[10],
        (float*)d_out);
}

// round 5
// speedup vs baseline: 1.4423x; 1.0815x over previous
#include <cuda_runtime.h>

// Problem constants
#define TT 512
#define DD 16
#define HH 48
#define NB 16
#define NBI 4
#define NTHREADS 384   // two independent halves of 192 threads (6 warps each)
#define NCTA 128

typedef unsigned long long ull;

// SMEM byte offsets
#define W1I_B 0                   // [8 kp][96 jj2][16B]
#define WR_B  12288               // [24 kp][96 jj2][3 mat][16B]
#define BB1_B (WR_B + 110592)
#define BB2_B (BB1_B + 1536)
#define H1_B  (BB2_B + 1536)      // [2 buf][16 bb][52 floats]
#define H2_B  (H1_B + 2*3328)
#define XD_B  (H2_B + 2*3328)     // [2 buf][16 bb][28 floats]
#define SMEM_BYTES (XD_B + 2*1792)

#define HBUF 3328
#define HROW 208
#define XBUF 1792
#define XROW 112

__device__ __forceinline__ float fsig(float x) {
    return __fdividef(1.0f, 1.0f + __expf(-x));
}
__device__ __forceinline__ float ftanh_(float x) {
    return __fdividef(2.0f, 1.0f + __expf(-2.0f * x)) - 1.0f;
}
__device__ __forceinline__ void ffma2(ull& a, ull w, ull h) {
    asm("fma.rn.f32x2 %0, %1, %2, %0;" : "+l"(a) : "l"(w), "l"(h));
}
__device__ __forceinline__ float2 unpk(ull v) {
    float2 r;
    asm("mov.b64 {%0, %1}, %2;" : "=f"(r.x), "=f"(r.y) : "l"(v));
    return r;
}
__device__ __forceinline__ ull pk2(float a, float b) {
    ull d;
    asm("mov.b64 %0, {%1, %2};" : "=l"(d) : "f"(a), "f"(b));
    return d;
}
__device__ __forceinline__ void half_bar(int id) {
    asm volatile("bar.sync %0, 192;" :: "r"(id) : "memory");
}

__global__ void __launch_bounds__(NTHREADS, 1)
lstm2_kernel(const float* __restrict__ x,
             const float* __restrict__ Wih0, const float* __restrict__ Whh0,
             const float* __restrict__ bih0, const float* __restrict__ bhh0,
             const float* __restrict__ Wih1, const float* __restrict__ Whh1,
             const float* __restrict__ bih1, const float* __restrict__ bhh1,
             const float* __restrict__ fcw,  const float* __restrict__ fcb,
             float* __restrict__ out)
{
    extern __shared__ char sm[];
    float* smf = (float*)sm;
    const int tid = threadIdx.x;

    // ---- repack W1I ----
    for (int i = tid; i < 8*96*4; i += NTHREADS) {
        int f = i & 3, jj2 = (i >> 2) % 96, kp = i / 384;
        int j = jj2 >> 1, gp = jj2 & 1;
        int gate = gp*2 + (f >> 1), k = kp*2 + (f & 1);
        smf[(W1I_B >> 2) + i] = Wih0[(gate*HH + j)*DD + k];
    }
    // ---- repack WR (Whh0, Wih1, Whh1 interleaved) ----
    for (int i = tid; i < 24*96*3*4; i += NTHREADS) {
        int f = i & 3, m = (i >> 2) % 3, jj2 = (i / 12) % 96, kp = i / 1152;
        int j = jj2 >> 1, gp = jj2 & 1;
        int gate = gp*2 + (f >> 1), k = kp*2 + (f & 1);
        int r = (gate*HH + j)*HH + k;
        smf[(WR_B >> 2) + i] = (m == 0) ? Whh0[r] : (m == 1) ? Wih1[r] : Whh1[r];
    }
    // ---- biases ----
    for (int i = tid; i < 96*4; i += NTHREADS) {
        int f = i & 3, jj2 = i >> 2;
        int j = jj2 >> 1, gp = jj2 & 1;
        int gate = gp*2 + (f >> 1);
        float v1 = (f & 1) ? 0.f : (bih0[gate*HH + j] + bhh0[gate*HH + j]);
        float v2 = (f & 1) ? 0.f : (bih1[gate*HH + j] + bhh1[gate*HH + j]);
        smf[(BB1_B >> 2) + i] = v1;
        smf[(BB2_B >> 2) + i] = v2;
    }
    for (int i = tid; i < (4*HBUF) >> 2; i += NTHREADS)
        smf[(H1_B >> 2) + i] = 0.f;

    // ---- lane mapping ----
    const int gp = tid & 1;
    const int jl = (tid >> 1) & 7;
    const int gh = (tid >> 4) & 1;
    const int w  = tid >> 5;
    const int j  = (w % 6) * 8 + jl;
    const int grp = (w / 6) * 2 + gh;
    const int bl0 = grp * NBI;
    const int jj2 = j*2 + gp;

    const int half  = (tid >= 192);          // warps 0-5 vs 6-11
    const int barid = 1 + half;
    const int htid  = tid - half*192;

    const float* xg = x + ((long)blockIdx.x * NB) * (long)(TT*DD);
    // per-half x staging: 128 threads handle this half's 8 batch rows
    const int xact = (htid < 128);
    const int xb_  = half*8 + (htid >> 4);
    const int xd   = htid & 15;

    if (xact)
        *(float*)(sm + XD_B + xb_*XROW + xd*4) = xg[(long)xb_*(TT*DD) + xd];
    __syncthreads();

    const char* pWI = sm + W1I_B + jj2*16;
    const char* pWR = sm + WR_B + jj2*48;
    const ulonglong2 b1 = *(const ulonglong2*)(sm + BB1_B + jj2*16);
    const ulonglong2 b2 = *(const ulonglong2*)(sm + BB2_B + jj2*16);

    float c1[2] = {0.f, 0.f};
    float c2[2] = {0.f, 0.f};

    for (int t = 0; t <= TT; ++t) {
        const int cur = t & 1, prv = cur ^ 1;

        float xpre = 0.f;
        if (t + 1 < TT && xact)
            xpre = xg[(long)xb_*(TT*DD) + (long)(t+1)*DD + xd];

        ull a1I[NBI], a1F[NBI], a2I[NBI], a2F[NBI];
        #pragma unroll
        for (int bb = 0; bb < NBI; ++bb) {
            a1I[bb] = b1.x; a1F[bb] = b1.y;
            a2I[bb] = b2.x; a2F[bb] = b2.y;
        }

        // ===== layer1 input: x =====
        {
            const char* xb = sm + XD_B + cur*XBUF + bl0*XROW;
            #pragma unroll
            for (int kx = 0; kx < 4; ++kx) {
                const ulonglong2 w0 = *(const ulonglong2*)(pWI + (2*kx  )*1536);
                const ulonglong2 w1 = *(const ulonglong2*)(pWI + (2*kx+1)*1536);
                #pragma unroll
                for (int bb = 0; bb < NBI; ++bb) {
                    const ulonglong2 xv = *(const ulonglong2*)(xb + bb*XROW + kx*16);
                    ffma2(a1I[bb], w0.x, xv.x); ffma2(a1F[bb], w0.y, xv.x);
                    ffma2(a1I[bb], w1.x, xv.y); ffma2(a1F[bb], w1.y, xv.y);
                }
            }
        }

        // ===== fused recurrent =====
        {
            const char* h1b = sm + H1_B + prv*HBUF + bl0*HROW;
            const char* h2b = sm + H2_B + cur*HBUF + bl0*HROW;
            #pragma unroll 3
            for (int kb = 0; kb < 12; ++kb) {
                const char* wb = pWR + kb*9216;
                const ulonglong2 wa0 = *(const ulonglong2*)(wb);
                const ulonglong2 wb0 = *(const ulonglong2*)(wb + 16);
                const ulonglong2 wc0 = *(const ulonglong2*)(wb + 32);
                const ulonglong2 wa1 = *(const ulonglong2*)(wb + 4608);
                const ulonglong2 wb1 = *(const ulonglong2*)(wb + 4624);
                const ulonglong2 wc1 = *(const ulonglong2*)(wb + 4640);
                #pragma unroll
                for (int bb = 0; bb < NBI; ++bb) {
                    const ulonglong2 h1v = *(const ulonglong2*)(h1b + bb*HROW + kb*16);
                    const ulonglong2 h2v = *(const ulonglong2*)(h2b + bb*HROW + kb*16);
                    ffma2(a1I[bb], wa0.x, h1v.x); ffma2(a1F[bb], wa0.y, h1v.x);
                    ffma2(a1I[bb], wa1.x, h1v.y); ffma2(a1F[bb], wa1.y, h1v.y);
                    ffma2(a2I[bb], wb0.x, h1v.x); ffma2(a2F[bb], wb0.y, h1v.x);
                    ffma2(a2I[bb], wb1.x, h1v.y); ffma2(a2F[bb], wb1.y, h1v.y);
                    ffma2(a2I[bb], wc0.x, h2v.x); ffma2(a2F[bb], wc0.y, h2v.x);
                    ffma2(a2I[bb], wc1.x, h2v.y); ffma2(a2F[bb], wc1.y, h2v.y);
                }
            }
        }

        char* h1n = sm + H1_B + cur*HBUF + bl0*HROW;
        char* h2n = sm + H2_B + prv*HBUF + bl0*HROW;

        if (t > 0 && t < TT) {
            // ===== steady state: both epilogues fused & interleaved =====
            ull p1[NBI], e1[NBI], p2[NBI], e2[NBI];
            #pragma unroll
            for (int bb = 0; bb < NBI; ++bb) {
                float2 v1I = unpk(a1I[bb]), v1F = unpk(a1F[bb]);
                float2 v2I = unpk(a2I[bb]), v2F = unpk(a2F[bb]);
                p1[bb] = pk2(v1I.x + v1I.y, v1F.x + v1F.y);
                p2[bb] = pk2(v2I.x + v2I.y, v2F.x + v2F.y);
            }
            #pragma unroll
            for (int bb = 0; bb < NBI; ++bb) {
                e1[bb] = __shfl_xor_sync(0xFFFFFFFFu, p1[bb], 1);
                e2[bb] = __shfl_xor_sync(0xFFFFFFFFu, p2[bb], 1);
            }
            #pragma unroll
            for (int o = 0; o < 2; ++o) {
                const int bb = gp*2 + o;
                float2 pIF1 = unpk(gp ? e1[bb] : p1[bb]);
                float2 pGO1 = unpk(gp ? p1[bb] : e1[bb]);
                float2 pIF2 = unpk(gp ? e2[bb] : p2[bb]);
                float2 pGO2 = unpk(gp ? p2[bb] : e2[bb]);
                float iv1 = fsig(pIF1.x), iv2 = fsig(pIF2.x);
                float fv1 = fsig(pIF1.y), fv2 = fsig(pIF2.y);
                float gv1 = ftanh_(pGO1.x), gv2 = ftanh_(pGO2.x);
                float ov1 = fsig(pGO1.y),  ov2 = fsig(pGO2.y);
                c1[o] = fmaf(fv1, c1[o], iv1 * gv1);
                c2[o] = fmaf(fv2, c2[o], iv2 * gv2);
                *(float*)(h1n + bb*HROW + j*4) = ov1 * ftanh_(c1[o]);
                *(float*)(h2n + bb*HROW + j*4) = ov2 * ftanh_(c2[o]);
            }
        } else if (t < TT) {
            // t == 0: layer1 only
            ull p1[NBI], e1[NBI];
            #pragma unroll
            for (int bb = 0; bb < NBI; ++bb) {
                float2 vI = unpk(a1I[bb]), vF = unpk(a1F[bb]);
                p1[bb] = pk2(vI.x + vI.y, vF.x + vF.y);
            }
            #pragma unroll
            for (int bb = 0; bb < NBI; ++bb)
                e1[bb] = __shfl_xor_sync(0xFFFFFFFFu, p1[bb], 1);
            #pragma unroll
            for (int o = 0; o < 2; ++o) {
                const int bb = gp*2 + o;
                float2 pIF = unpk(gp ? e1[bb] : p1[bb]);
                float2 pGO = unpk(gp ? p1[bb] : e1[bb]);
                float iv = fsig(pIF.x), fv = fsig(pIF.y);
                float gv = ftanh_(pGO.x), ov = fsig(pGO.y);
                c1[o] = fmaf(fv, c1[o], iv * gv);
                *(float*)(h1n + bb*HROW + j*4) = ov * ftanh_(c1[o]);
            }
        } else {
            // t == TT: layer2 only
            ull p2[NBI], e2[NBI];
            #pragma unroll
            for (int bb = 0; bb < NBI; ++bb) {
                float2 vI = unpk(a2I[bb]), vF = unpk(a2F[bb]);
                p2[bb] = pk2(vI.x + vI.y, vF.x + vF.y);
            }
            #pragma unroll
            for (int bb = 0; bb < NBI; ++bb)
                e2[bb] = __shfl_xor_sync(0xFFFFFFFFu, p2[bb], 1);
            #pragma unroll
            for (int o = 0; o < 2; ++o) {
                const int bb = gp*2 + o;
                float2 pIF = unpk(gp ? e2[bb] : p2[bb]);
                float2 pGO = unpk(gp ? p2[bb] : e2[bb]);
                float iv = fsig(pIF.x), fv = fsig(pIF.y);
                float gv = ftanh_(pGO.x), ov = fsig(pGO.y);
                c2[o] = fmaf(fv, c2[o], iv * gv);
                *(float*)(h2n + bb*HROW + j*4) = ov * ftanh_(c2[o]);
            }
        }

        if (t + 1 < TT && xact)
            *(float*)(sm + XD_B + prv*XBUF + xb_*XROW + xd*4) = xpre;

        // per-half barrier: the two batch-halves run on independent clocks
        half_bar(barid);
    }

    __syncthreads();
    // ===== final FC + sigmoid: h2[511] in buf 1 =====
    if (tid < NB) {
        const float* h2f = (const float*)(sm + H2_B + HBUF + tid*HROW);
        float acc = fcb[0];
        #pragma unroll
        for (int jj = 0; jj < HH; ++jj)
            acc = fmaf(h2f[jj], fcw[jj], acc);
        out[blockIdx.x * NB + tid] = fsig(acc);
    }
}

extern "C" void kernel_launch(void* const* d_in, const int* in_sizes, int n_in,
                              void* d_out, int out_size) {
    (void)in_sizes; (void)n_in; (void)out_size;
    cudaFuncSetAttribute(lstm2_kernel,
                         cudaFuncAttributeMaxDynamicSharedMemorySize, SMEM_BYTES);
    lstm2_kernel<<<NCTA, NTHREADS, SMEM_BYTES>>>(
        (const float*)d_in[0],
        (const float*)d_in[1], (const float*)d_in[2],
        (const float*)d_in[3], (const float*)d_in[4],
        (const float*)d_in[5], (const float*)d_in[6],
        (const float*)d_in[7], (const float*)d_in[8],
        (const float*)d_in[9], (const float*)d_in[10],
        (float*)d_out);
}